// round 16
// baseline (speedup 1.0000x reference)
#include <cuda_runtime.h>
#include <cstdint>

// Problem constants
#define NMAX    100000
#define EMAX    1000000
#define IN_DIM  32
#define HID     64
#define NGRAPHS 128
#define LAT     32

#define LDAA 68     // A-tile row stride (floats): conflict-free A-fragment loads
#define LDAW 72     // W-tile row stride (floats): conflict-free B-fragment loads
// dynamic smem: sInHi | sInLo | sWHi | sWLo
#define OFF_INHI 0
#define OFF_INLO (64 * LDAA)
#define OFF_WHI  (2 * 64 * LDAA)
#define OFF_WLO  (2 * 64 * LDAA + 64 * LDAW)
#define SMEM_FLOATS (2 * 64 * LDAA + 2 * 64 * LDAW)
#define SMEM_BYTES (SMEM_FLOATS * 4)   // 71680

// Scratch (device globals — allocation-free rule)
__device__ __align__(16) float g_hA[(size_t)NMAX * HID];
__device__ __align__(16) float g_hB[(size_t)NMAX * HID];
__device__ __align__(16) float g_pooled[NGRAPHS * HID];
__device__ int g_deg[NMAX];
__device__ int g_off[NMAX];
__device__ int g_cur[NMAX];
__device__ int g_csr[EMAX];
__device__ int g_part[128];

__device__ __forceinline__ void red_add_v2(float* p, float2 v) {
    asm volatile("red.global.add.v2.f32 [%0], {%1,%2};"
                 :: "l"(p), "f"(v.x), "f"(v.y) : "memory");
}

// 3xTF32 split: hi = tf32(x), lo = tf32(x - hi)
__device__ __forceinline__ float2 tf32_split(float x) {
    uint32_t h;
    asm("cvt.rna.tf32.f32 %0, %1;" : "=r"(h) : "f"(x));
    float hf = __uint_as_float(h);
    float lo = x - hf;
    uint32_t l;
    asm("cvt.rna.tf32.f32 %0, %1;" : "=r"(l) : "f"(lo));
    return make_float2(hf, __uint_as_float(l));
}

// m16n8k8 tf32 MMA (HMMA pipe; baseline PTX, compiles for sm_103 non-a)
__device__ __forceinline__ void hmma(float c[4],
                                     uint32_t a0, uint32_t a1, uint32_t a2, uint32_t a3,
                                     uint32_t b0, uint32_t b1) {
    asm("mma.sync.aligned.m16n8k8.row.col.f32.tf32.tf32.f32 "
        "{%0,%1,%2,%3}, {%4,%5,%6,%7}, {%8,%9}, {%0,%1,%2,%3};"
        : "+f"(c[0]), "+f"(c[1]), "+f"(c[2]), "+f"(c[3])
        : "r"(a0), "r"(a1), "r"(a2), "r"(a3), "r"(b0), "r"(b1));
}

// ===========================================================================
// Zero / CSR-build kernels
// ===========================================================================
__global__ void k_zero_init(int n) {
    int i = blockIdx.x * blockDim.x + threadIdx.x;
    if (i < n) g_deg[i] = 0;
    if (i < NGRAPHS * HID / 4)
        reinterpret_cast<float4*>(g_pooled)[i] = make_float4(0.f, 0.f, 0.f, 0.f);
}

__global__ void k_hist(const int* __restrict__ ei, int nEdges, int nNodes) {
    int e = blockIdx.x * blockDim.x + threadIdx.x;
    if (e >= nEdges) return;
    int src = __ldg(&ei[e]);
    int dst = __ldg(&ei[(size_t)nEdges + e]);
    if ((unsigned)src >= (unsigned)nNodes || (unsigned)dst >= (unsigned)nNodes) return;
    atomicAdd(&g_deg[dst], 1);
}

__global__ __launch_bounds__(1024) void k_scan1(int n) {
    __shared__ int s[1024];
    int t = threadIdx.x;
    int i = blockIdx.x * 1024 + t;
    int v = (i < n) ? g_deg[i] : 0;
    s[t] = v;
    __syncthreads();
    for (int off = 1; off < 1024; off <<= 1) {
        int x = (t >= off) ? s[t - off] : 0;
        __syncthreads();
        s[t] += x;
        __syncthreads();
    }
    if (i < n) g_off[i] = s[t] - v;
    if (t == 1023) g_part[blockIdx.x] = s[1023];
}

__global__ __launch_bounds__(128) void k_scan2(int nChunks) {
    __shared__ int s[128];
    int t = threadIdx.x;
    int v = (t < nChunks) ? g_part[t] : 0;
    s[t] = v;
    __syncthreads();
    for (int off = 1; off < 128; off <<= 1) {
        int x = (t >= off) ? s[t - off] : 0;
        __syncthreads();
        s[t] += x;
        __syncthreads();
    }
    if (t < nChunks) g_part[t] = s[t] - v;
}

__global__ void k_scan3(int n) {
    int i = blockIdx.x * blockDim.x + threadIdx.x;
    if (i >= n) return;
    int o = g_off[i] + g_part[i >> 10];
    g_off[i] = o;
    g_cur[i] = o;
}

__global__ void k_fill(const int* __restrict__ ei, int nEdges, int nNodes) {
    int e = blockIdx.x * blockDim.x + threadIdx.x;
    if (e >= nEdges) return;
    int src = __ldg(&ei[e]);
    int dst = __ldg(&ei[(size_t)nEdges + e]);
    if ((unsigned)src >= (unsigned)nNodes || (unsigned)dst >= (unsigned)nNodes) return;
    int pos = atomicAdd(&g_cur[dst], 1);
    if (pos < EMAX) g_csr[pos] = src;
}

// ===========================================================================
// Input projection: h = x @ w_in + b_in   [N,32] @ [32,64]  -> g_hA
// ===========================================================================
__global__ __launch_bounds__(256) void k_proj(const float* __restrict__ x,
                                              const float* __restrict__ w_in,
                                              const float* __restrict__ b_in,
                                              int nNodes) {
    __shared__ __align__(16) float sX[64 * IN_DIM];
    __shared__ __align__(16) float sW[IN_DIM * HID];
    int tid = threadIdx.x;
    int nb = blockIdx.x * 64;

    for (int i = tid; i < 64 * IN_DIM; i += 256) {
        int n = nb + i / IN_DIM;
        sX[i] = (n < nNodes) ? x[(size_t)nb * IN_DIM + i] : 0.f;
    }
    for (int i = tid; i < IN_DIM * HID; i += 256) sW[i] = w_in[i];
    __syncthreads();

    int fq = tid & 15, ng = tid >> 4;
    float acc[4][4];
    float4 bb = *reinterpret_cast<const float4*>(b_in + 4 * fq);
#pragma unroll
    for (int n = 0; n < 4; n++) {
        acc[n][0] = bb.x; acc[n][1] = bb.y; acc[n][2] = bb.z; acc[n][3] = bb.w;
    }
#pragma unroll
    for (int k = 0; k < IN_DIM; k += 4) {
        float4 w0 = *reinterpret_cast<const float4*>(&sW[(k + 0) * HID + 4 * fq]);
        float4 w1 = *reinterpret_cast<const float4*>(&sW[(k + 1) * HID + 4 * fq]);
        float4 w2 = *reinterpret_cast<const float4*>(&sW[(k + 2) * HID + 4 * fq]);
        float4 w3 = *reinterpret_cast<const float4*>(&sW[(k + 3) * HID + 4 * fq]);
#pragma unroll
        for (int n = 0; n < 4; n++) {
            float4 a = *reinterpret_cast<const float4*>(&sX[(ng * 4 + n) * IN_DIM + k]);
            acc[n][0] += a.x * w0.x + a.y * w1.x + a.z * w2.x + a.w * w3.x;
            acc[n][1] += a.x * w0.y + a.y * w1.y + a.z * w2.y + a.w * w3.y;
            acc[n][2] += a.x * w0.z + a.y * w1.z + a.z * w2.z + a.w * w3.z;
            acc[n][3] += a.x * w0.w + a.y * w1.w + a.z * w2.w + a.w * w3.w;
        }
    }
#pragma unroll
    for (int n = 0; n < 4; n++) {
        int node = nb + ng * 4 + n;
        if (node < nNodes)
            *reinterpret_cast<float4*>(&g_hA[(size_t)node * HID + 4 * fq]) =
                make_float4(acc[n][0], acc[n][1], acc[n][2], acc[n][3]);
    }
}

// ===========================================================================
// 3xTF32 tensor-core GEMM core: one warp computes 4 m16n8 C-tiles
// ===========================================================================
__device__ __forceinline__ void tcgemm(float c[4][4],
                                       const float* __restrict__ sAhi,
                                       const float* __restrict__ sAlo,
                                       const float* __restrict__ sBhi,
                                       const float* __restrict__ sBlo,
                                       int m, int nbase, int gid, int tig) {
#pragma unroll
    for (int s = 0; s < 8; s++) {
        int k = 8 * s;
        int ar0 = (m + gid) * LDAA + k + tig;
        int ar1 = ar0 + 8 * LDAA;
        uint32_t ah0 = __float_as_uint(sAhi[ar0]);
        uint32_t ah1 = __float_as_uint(sAhi[ar1]);
        uint32_t ah2 = __float_as_uint(sAhi[ar0 + 4]);
        uint32_t ah3 = __float_as_uint(sAhi[ar1 + 4]);
        uint32_t al0 = __float_as_uint(sAlo[ar0]);
        uint32_t al1 = __float_as_uint(sAlo[ar1]);
        uint32_t al2 = __float_as_uint(sAlo[ar0 + 4]);
        uint32_t al3 = __float_as_uint(sAlo[ar1 + 4]);
#pragma unroll
        for (int j = 0; j < 4; j++) {
            int bo = (k + tig) * LDAW + nbase + 8 * j + gid;
            uint32_t bh0 = __float_as_uint(sBhi[bo]);
            uint32_t bh1 = __float_as_uint(sBhi[bo + 4 * LDAW]);
            uint32_t bl0 = __float_as_uint(sBlo[bo]);
            uint32_t bl1 = __float_as_uint(sBlo[bo + 4 * LDAW]);
            hmma(c[j], ah0, ah1, ah2, ah3, bh0, bh1);
            hmma(c[j], ah0, ah1, ah2, ah3, bl0, bl1);
            hmma(c[j], al0, al1, al2, al3, bh0, bh1);
        }
    }
}

// ===========================================================================
// Fused gather + GIN MLP, tensor-core version (reads hin, writes hout):
//   agg = sum_{src in CSR(dst)} hin[src]
//   hout = relu(relu((hin+agg)w1+b1)w2+b2) + hin ; last layer pools.
// Gather: one warp per node — coalesced idx load + shfl broadcast (MLP=degree).
// ===========================================================================
__global__ __launch_bounds__(256) void k_mlp_tc(const float* __restrict__ hin,
                                                float* __restrict__ hout,
                                                const float* __restrict__ w1,
                                                const float* __restrict__ b1,
                                                const float* __restrict__ w2,
                                                const float* __restrict__ b2,
                                                const int* __restrict__ batch,
                                                int isLast, int nNodes) {
    extern __shared__ __align__(16) float sm[];
    float* sInHi = sm + OFF_INHI;
    float* sInLo = sm + OFF_INLO;
    float* sWHi  = sm + OFF_WHI;
    float* sWLo  = sm + OFF_WLO;
    int tid = threadIdx.x;
    int nb = blockIdx.x * 64;

    // stage w1 (split hi/lo)
#pragma unroll
    for (int j = 0; j < 4; j++) {
        int idx = tid + j * 256;              // float4 index, 1024 total
        int k = idx >> 4;
        int n4 = (idx & 15) << 2;
        float4 w = __ldg(reinterpret_cast<const float4*>(w1) + idx);
        float2 s0 = tf32_split(w.x), s1 = tf32_split(w.y),
               s2 = tf32_split(w.z), s3 = tf32_split(w.w);
        *(float4*)&sWHi[k * LDAW + n4] = make_float4(s0.x, s1.x, s2.x, s3.x);
        *(float4*)&sWLo[k * LDAW + n4] = make_float4(s0.y, s1.y, s2.y, s3.y);
    }

    // gather: one warp per node, 8 passes; idx coalesced + shfl broadcast
    {
        int gw = tid >> 5, lane = tid & 31;
#pragma unroll
        for (int pass = 0; pass < 8; pass++) {
            int nl = pass * 8 + gw;
            int node = nb + nl;                     // warp-uniform
            float2 acc = make_float2(0.f, 0.f);
            if (node < nNodes) {
                acc = *reinterpret_cast<const float2*>(
                    &hin[(size_t)node * HID + 2 * lane]);    // self term
                int s = __ldg(&g_off[node]);
                int d = __ldg(&g_deg[node]);
                for (int base = 0; base < d; base += 32) {
                    int rem = d - base;
                    int cnt = rem < 32 ? rem : 32;
                    int idx = 0;
                    if (lane < cnt) idx = __ldg(&g_csr[s + base + lane]);
                    for (int i = 0; i < cnt; i++) {
                        int src = __shfl_sync(0xffffffffu, idx, i);
                        float2 v = *reinterpret_cast<const float2*>(
                            &hin[(size_t)src * HID + 2 * lane]);
                        acc.x += v.x; acc.y += v.y;
                    }
                }
            }
            float2 s0 = tf32_split(acc.x), s1 = tf32_split(acc.y);
            *(float2*)&sInHi[nl * LDAA + 2 * lane] = make_float2(s0.x, s1.x);
            *(float2*)&sInLo[nl * LDAA + 2 * lane] = make_float2(s0.y, s1.y);
        }
    }
    __syncthreads();

    int wid = tid >> 5, lane = tid & 31;
    int gid = lane >> 2, tig = lane & 3;
    int m = (wid & 3) * 16;
    int nbase = (wid >> 2) * 32;

    float c[4][4];
    // ---- phase 1: mid = relu(in @ w1 + b1) ----
#pragma unroll
    for (int j = 0; j < 4; j++) {
        float2 bb = __ldg(reinterpret_cast<const float2*>(&b1[nbase + 8 * j + 2 * tig]));
        c[j][0] = bb.x; c[j][1] = bb.y; c[j][2] = bb.x; c[j][3] = bb.y;
    }
    tcgemm(c, sInHi, sInLo, sWHi, sWLo, m, nbase, gid, tig);
    __syncthreads();

    // epi1: relu + split back into A tiles; stage w2 into W tiles
#pragma unroll
    for (int j = 0; j < 4; j++) {
        int n0 = nbase + 8 * j + 2 * tig;
        int r0 = m + gid, r1 = r0 + 8;
        float2 s0 = tf32_split(fmaxf(c[j][0], 0.f));
        float2 s1 = tf32_split(fmaxf(c[j][1], 0.f));
        float2 s2 = tf32_split(fmaxf(c[j][2], 0.f));
        float2 s3 = tf32_split(fmaxf(c[j][3], 0.f));
        *(float2*)&sInHi[r0 * LDAA + n0] = make_float2(s0.x, s1.x);
        *(float2*)&sInLo[r0 * LDAA + n0] = make_float2(s0.y, s1.y);
        *(float2*)&sInHi[r1 * LDAA + n0] = make_float2(s2.x, s3.x);
        *(float2*)&sInLo[r1 * LDAA + n0] = make_float2(s2.y, s3.y);
    }
#pragma unroll
    for (int j = 0; j < 4; j++) {
        int idx = tid + j * 256;
        int k = idx >> 4;
        int n4 = (idx & 15) << 2;
        float4 w = __ldg(reinterpret_cast<const float4*>(w2) + idx);
        float2 s0 = tf32_split(w.x), s1 = tf32_split(w.y),
               s2 = tf32_split(w.z), s3 = tf32_split(w.w);
        *(float4*)&sWHi[k * LDAW + n4] = make_float4(s0.x, s1.x, s2.x, s3.x);
        *(float4*)&sWLo[k * LDAW + n4] = make_float4(s0.y, s1.y, s2.y, s3.y);
    }
    __syncthreads();

    // ---- phase 2: hout = relu(mid @ w2 + b2) + hin ----
#pragma unroll
    for (int j = 0; j < 4; j++) {
        float2 bb = __ldg(reinterpret_cast<const float2*>(&b2[nbase + 8 * j + 2 * tig]));
        c[j][0] = bb.x; c[j][1] = bb.y; c[j][2] = bb.x; c[j][3] = bb.y;
    }
    tcgemm(c, sInHi, sInLo, sWHi, sWLo, m, nbase, gid, tig);

    // epi2: relu + skip + store (+ pool on last layer)
#pragma unroll
    for (int j = 0; j < 4; j++) {
        int n0 = nbase + 8 * j + 2 * tig;
#pragma unroll
        for (int half = 0; half < 2; half++) {
            int r = m + gid + 8 * half;
            int node = nb + r;
            if (node < nNodes) {
                float cx = c[j][2 * half], cy = c[j][2 * half + 1];
                size_t gbi = (size_t)node * HID + n0;
                float2 skip = __ldg(reinterpret_cast<const float2*>(&hin[gbi]));
                float2 r2 = make_float2(fmaxf(cx, 0.f) + skip.x,
                                        fmaxf(cy, 0.f) + skip.y);
                *reinterpret_cast<float2*>(&hout[gbi]) = r2;
                if (isLast) {
                    int g = __ldg(&batch[node]);
                    if ((unsigned)g < NGRAPHS)
                        red_add_v2(&g_pooled[g * HID + n0], r2);
                }
            }
        }
    }
}

// ===========================================================================
// Final: out = pooled @ w_fc + b_fc   [128,64] @ [64,32]
// ===========================================================================
__global__ __launch_bounds__(256) void k_final(const float* __restrict__ w_fc,
                                               const float* __restrict__ b_fc,
                                               float* __restrict__ out) {
    int t = blockIdx.x * blockDim.x + threadIdx.x;
    if (t >= NGRAPHS * LAT) return;
    int g = t >> 5;
    int l = t & 31;
    float acc = b_fc[l];
#pragma unroll
    for (int k = 0; k < HID; k++)
        acc += g_pooled[g * HID + k] * w_fc[k * LAT + l];
    out[t] = acc;
}

// ===========================================================================
// Launch
// ===========================================================================
extern "C" void kernel_launch(void* const* d_in, const int* in_sizes, int n_in,
                              void* d_out, int out_size) {
    const float* x    = (const float*)d_in[0];
    const int*   ei   = (const int*)d_in[1];
    const int*   batch= (const int*)d_in[2];
    const float* w_in = (const float*)d_in[3];
    const float* b_in = (const float*)d_in[4];
    const float* w1   = (const float*)d_in[5];
    const float* b1   = (const float*)d_in[6];
    const float* w2   = (const float*)d_in[7];
    const float* b2   = (const float*)d_in[8];
    const float* w_fc = (const float*)d_in[9];
    const float* b_fc = (const float*)d_in[10];
    float* out = (float*)d_out;

    int nNodes = in_sizes[0] / IN_DIM;
    int nEdges = in_sizes[1] / 2;
    if (nNodes > NMAX) nNodes = NMAX;
    if (nEdges > EMAX) nEdges = EMAX;

    int nodeBlocks = (nNodes + 63) / 64;
    int edgeBlocks = (nEdges + 255) / 256;
    int nThreadBlocks = (nNodes + 255) / 256;
    int nChunks = (nNodes + 1023) / 1024;

    static int smemSet = 0;
    if (!smemSet) {
        cudaFuncSetAttribute(k_mlp_tc, cudaFuncAttributeMaxDynamicSharedMemorySize,
                             SMEM_BYTES);
        smemSet = 1;
    }

    float *hA, *hB;
    cudaGetSymbolAddress((void**)&hA, g_hA);
    cudaGetSymbolAddress((void**)&hB, g_hB);

    // CSR build (reused across all 3 layers)
    k_zero_init<<<nThreadBlocks, 256>>>(nNodes);
    k_hist<<<edgeBlocks, 256>>>(ei, nEdges, nNodes);
    k_scan1<<<nChunks, 1024>>>(nNodes);
    k_scan2<<<1, 128>>>(nChunks);
    k_scan3<<<nThreadBlocks, 256>>>(nNodes);
    k_fill<<<edgeBlocks, 256>>>(ei, nEdges, nNodes);

    k_proj<<<nodeBlocks, 256>>>(x, w_in, b_in, nNodes);

    const float* cur = hA;
    float* nxt = hB;
    for (int i = 0; i < 3; i++) {
        k_mlp_tc<<<nodeBlocks, 256, SMEM_BYTES>>>(
            cur, nxt,
            w1 + (size_t)i * HID * HID, b1 + (size_t)i * HID,
            w2 + (size_t)i * HID * HID, b2 + (size_t)i * HID,
            batch, (i == 2) ? 1 : 0, nNodes);
        const float* tmp = nxt;
        nxt = (float*)cur;
        cur = tmp;
    }

    k_final<<<(NGRAPHS * LAT + 255) / 256, 256>>>(w_fc, b_fc, out);
}

// round 17
// speedup vs baseline: 1.0041x; 1.0041x over previous
#include <cuda_runtime.h>
#include <cstdint>

// Problem constants
#define NMAX    100000
#define EMAX    1000000
#define IN_DIM  32
#define HID     64
#define NGRAPHS 128
#define LAT     32

#define LDAA 68     // A-tile row stride (floats): conflict-free A-fragment loads
#define LDAW 72     // W-tile row stride (floats): conflict-free B-fragment loads
#define EBUF 4096   // smem CSR slice buffer (ints)
// dynamic smem: sInHi | sInLo | sWHi | sWLo | sEdge
#define OFF_INHI 0
#define OFF_INLO (64 * LDAA)
#define OFF_WHI  (2 * 64 * LDAA)
#define OFF_WLO  (2 * 64 * LDAA + 64 * LDAW)
#define SMEM_FLOATS (2 * 64 * LDAA + 2 * 64 * LDAW)
#define SMEM_BYTES (SMEM_FLOATS * 4 + EBUF * 4)   // 71680 + 16384 = 88064

// Scratch (device globals — allocation-free rule)
__device__ __align__(16) float g_hA[(size_t)NMAX * HID];
__device__ __align__(16) float g_hB[(size_t)NMAX * HID];
__device__ __align__(16) float g_pooled[NGRAPHS * HID];
__device__ int g_deg[NMAX];
__device__ int g_off[NMAX];
__device__ int g_cur[NMAX];
__device__ int g_csr[EMAX];
__device__ int g_part[128];

__device__ __forceinline__ void red_add_v2(float* p, float2 v) {
    asm volatile("red.global.add.v2.f32 [%0], {%1,%2};"
                 :: "l"(p), "f"(v.x), "f"(v.y) : "memory");
}

// 3xTF32 split: hi = tf32(x), lo = tf32(x - hi)
__device__ __forceinline__ float2 tf32_split(float x) {
    uint32_t h;
    asm("cvt.rna.tf32.f32 %0, %1;" : "=r"(h) : "f"(x));
    float hf = __uint_as_float(h);
    float lo = x - hf;
    uint32_t l;
    asm("cvt.rna.tf32.f32 %0, %1;" : "=r"(l) : "f"(lo));
    return make_float2(hf, __uint_as_float(l));
}

// m16n8k8 tf32 MMA (HMMA pipe; baseline PTX, compiles for sm_103 non-a)
__device__ __forceinline__ void hmma(float c[4],
                                     uint32_t a0, uint32_t a1, uint32_t a2, uint32_t a3,
                                     uint32_t b0, uint32_t b1) {
    asm("mma.sync.aligned.m16n8k8.row.col.f32.tf32.tf32.f32 "
        "{%0,%1,%2,%3}, {%4,%5,%6,%7}, {%8,%9}, {%0,%1,%2,%3};"
        : "+f"(c[0]), "+f"(c[1]), "+f"(c[2]), "+f"(c[3])
        : "r"(a0), "r"(a1), "r"(a2), "r"(a3), "r"(b0), "r"(b1));
}

// ===========================================================================
// Zero / CSR-build kernels
// ===========================================================================
__global__ void k_zero_init(int n) {
    int i = blockIdx.x * blockDim.x + threadIdx.x;
    if (i < n) g_deg[i] = 0;
    if (i < NGRAPHS * HID / 4)
        reinterpret_cast<float4*>(g_pooled)[i] = make_float4(0.f, 0.f, 0.f, 0.f);
}

__global__ void k_hist(const int* __restrict__ ei, int nEdges, int nNodes) {
    int e = blockIdx.x * blockDim.x + threadIdx.x;
    if (e >= nEdges) return;
    int src = __ldg(&ei[e]);
    int dst = __ldg(&ei[(size_t)nEdges + e]);
    if ((unsigned)src >= (unsigned)nNodes || (unsigned)dst >= (unsigned)nNodes) return;
    atomicAdd(&g_deg[dst], 1);
}

__global__ __launch_bounds__(1024) void k_scan1(int n) {
    __shared__ int s[1024];
    int t = threadIdx.x;
    int i = blockIdx.x * 1024 + t;
    int v = (i < n) ? g_deg[i] : 0;
    s[t] = v;
    __syncthreads();
    for (int off = 1; off < 1024; off <<= 1) {
        int x = (t >= off) ? s[t - off] : 0;
        __syncthreads();
        s[t] += x;
        __syncthreads();
    }
    if (i < n) g_off[i] = s[t] - v;
    if (t == 1023) g_part[blockIdx.x] = s[1023];
}

__global__ __launch_bounds__(128) void k_scan2(int nChunks) {
    __shared__ int s[128];
    int t = threadIdx.x;
    int v = (t < nChunks) ? g_part[t] : 0;
    s[t] = v;
    __syncthreads();
    for (int off = 1; off < 128; off <<= 1) {
        int x = (t >= off) ? s[t - off] : 0;
        __syncthreads();
        s[t] += x;
        __syncthreads();
    }
    if (t < nChunks) g_part[t] = s[t] - v;
}

__global__ void k_scan3(int n) {
    int i = blockIdx.x * blockDim.x + threadIdx.x;
    if (i >= n) return;
    int o = g_off[i] + g_part[i >> 10];
    g_off[i] = o;
    g_cur[i] = o;
}

__global__ void k_fill(const int* __restrict__ ei, int nEdges, int nNodes) {
    int e = blockIdx.x * blockDim.x + threadIdx.x;
    if (e >= nEdges) return;
    int src = __ldg(&ei[e]);
    int dst = __ldg(&ei[(size_t)nEdges + e]);
    if ((unsigned)src >= (unsigned)nNodes || (unsigned)dst >= (unsigned)nNodes) return;
    int pos = atomicAdd(&g_cur[dst], 1);
    if (pos < EMAX) g_csr[pos] = src;
}

// ===========================================================================
// Input projection: h = x @ w_in + b_in   [N,32] @ [32,64]  -> g_hA
// ===========================================================================
__global__ __launch_bounds__(256) void k_proj(const float* __restrict__ x,
                                              const float* __restrict__ w_in,
                                              const float* __restrict__ b_in,
                                              int nNodes) {
    __shared__ __align__(16) float sX[64 * IN_DIM];
    __shared__ __align__(16) float sW[IN_DIM * HID];
    int tid = threadIdx.x;
    int nb = blockIdx.x * 64;

    for (int i = tid; i < 64 * IN_DIM; i += 256) {
        int n = nb + i / IN_DIM;
        sX[i] = (n < nNodes) ? x[(size_t)nb * IN_DIM + i] : 0.f;
    }
    for (int i = tid; i < IN_DIM * HID; i += 256) sW[i] = w_in[i];
    __syncthreads();

    int fq = tid & 15, ng = tid >> 4;
    float acc[4][4];
    float4 bb = *reinterpret_cast<const float4*>(b_in + 4 * fq);
#pragma unroll
    for (int n = 0; n < 4; n++) {
        acc[n][0] = bb.x; acc[n][1] = bb.y; acc[n][2] = bb.z; acc[n][3] = bb.w;
    }
#pragma unroll
    for (int k = 0; k < IN_DIM; k += 4) {
        float4 w0 = *reinterpret_cast<const float4*>(&sW[(k + 0) * HID + 4 * fq]);
        float4 w1 = *reinterpret_cast<const float4*>(&sW[(k + 1) * HID + 4 * fq]);
        float4 w2 = *reinterpret_cast<const float4*>(&sW[(k + 2) * HID + 4 * fq]);
        float4 w3 = *reinterpret_cast<const float4*>(&sW[(k + 3) * HID + 4 * fq]);
#pragma unroll
        for (int n = 0; n < 4; n++) {
            float4 a = *reinterpret_cast<const float4*>(&sX[(ng * 4 + n) * IN_DIM + k]);
            acc[n][0] += a.x * w0.x + a.y * w1.x + a.z * w2.x + a.w * w3.x;
            acc[n][1] += a.x * w0.y + a.y * w1.y + a.z * w2.y + a.w * w3.y;
            acc[n][2] += a.x * w0.z + a.y * w1.z + a.z * w2.z + a.w * w3.z;
            acc[n][3] += a.x * w0.w + a.y * w1.w + a.z * w2.w + a.w * w3.w;
        }
    }
#pragma unroll
    for (int n = 0; n < 4; n++) {
        int node = nb + ng * 4 + n;
        if (node < nNodes)
            *reinterpret_cast<float4*>(&g_hA[(size_t)node * HID + 4 * fq]) =
                make_float4(acc[n][0], acc[n][1], acc[n][2], acc[n][3]);
    }
}

// ===========================================================================
// 3xTF32 tensor-core GEMM core: one warp computes 4 m16n8 C-tiles
// ===========================================================================
__device__ __forceinline__ void tcgemm(float c[4][4],
                                       const float* __restrict__ sAhi,
                                       const float* __restrict__ sAlo,
                                       const float* __restrict__ sBhi,
                                       const float* __restrict__ sBlo,
                                       int m, int nbase, int gid, int tig) {
#pragma unroll
    for (int s = 0; s < 8; s++) {
        int k = 8 * s;
        int ar0 = (m + gid) * LDAA + k + tig;
        int ar1 = ar0 + 8 * LDAA;
        uint32_t ah0 = __float_as_uint(sAhi[ar0]);
        uint32_t ah1 = __float_as_uint(sAhi[ar1]);
        uint32_t ah2 = __float_as_uint(sAhi[ar0 + 4]);
        uint32_t ah3 = __float_as_uint(sAhi[ar1 + 4]);
        uint32_t al0 = __float_as_uint(sAlo[ar0]);
        uint32_t al1 = __float_as_uint(sAlo[ar1]);
        uint32_t al2 = __float_as_uint(sAlo[ar0 + 4]);
        uint32_t al3 = __float_as_uint(sAlo[ar1 + 4]);
#pragma unroll
        for (int j = 0; j < 4; j++) {
            int bo = (k + tig) * LDAW + nbase + 8 * j + gid;
            uint32_t bh0 = __float_as_uint(sBhi[bo]);
            uint32_t bh1 = __float_as_uint(sBhi[bo + 4 * LDAW]);
            uint32_t bl0 = __float_as_uint(sBlo[bo]);
            uint32_t bl1 = __float_as_uint(sBlo[bo + 4 * LDAW]);
            hmma(c[j], ah0, ah1, ah2, ah3, bh0, bh1);
            hmma(c[j], ah0, ah1, ah2, ah3, bl0, bl1);
            hmma(c[j], al0, al1, al2, al3, bh0, bh1);
        }
    }
}

// ===========================================================================
// Fused gather + GIN MLP, tensor-core version (reads hin, writes hout):
//   agg = sum_{src in CSR(dst)} hin[src]
//   hout = relu(relu((hin+agg)w1+b1)w2+b2) + hin ; last layer pools.
// Gather: 16-lane groups; block CSR slice staged in smem; unroll-4 row loads.
// ===========================================================================
__global__ __launch_bounds__(256) void k_mlp_tc(const float* __restrict__ hin,
                                                float* __restrict__ hout,
                                                const float* __restrict__ w1,
                                                const float* __restrict__ b1,
                                                const float* __restrict__ w2,
                                                const float* __restrict__ b2,
                                                const int* __restrict__ batch,
                                                int isLast, int nNodes) {
    extern __shared__ __align__(16) float sm[];
    float* sInHi = sm + OFF_INHI;
    float* sInLo = sm + OFF_INLO;
    float* sWHi  = sm + OFF_WHI;
    float* sWLo  = sm + OFF_WLO;
    int* sEdge   = reinterpret_cast<int*>(sm + SMEM_FLOATS);
    int tid = threadIdx.x;
    int nb = blockIdx.x * 64;

    // stage block CSR slice (contiguous because CSR is dst-sorted)
    int lastNode = nb + 63;
    if (lastNode >= nNodes) lastNode = nNodes - 1;
    int eBase = __ldg(&g_off[nb]);
    int eEnd  = __ldg(&g_off[lastNode]) + __ldg(&g_deg[lastNode]);
    int eCnt  = eEnd - eBase;
    int eStage = eCnt < EBUF ? eCnt : EBUF;
    for (int i = tid; i < eStage; i += 256) sEdge[i] = __ldg(&g_csr[eBase + i]);

    // stage w1 (split hi/lo)
#pragma unroll
    for (int j = 0; j < 4; j++) {
        int idx = tid + j * 256;              // float4 index, 1024 total
        int k = idx >> 4;
        int n4 = (idx & 15) << 2;
        float4 w = __ldg(reinterpret_cast<const float4*>(w1) + idx);
        float2 s0 = tf32_split(w.x), s1 = tf32_split(w.y),
               s2 = tf32_split(w.z), s3 = tf32_split(w.w);
        *(float4*)&sWHi[k * LDAW + n4] = make_float4(s0.x, s1.x, s2.x, s3.x);
        *(float4*)&sWLo[k * LDAW + n4] = make_float4(s0.y, s1.y, s2.y, s3.y);
    }
    __syncthreads();    // sEdge visible to all

    // gather: 16 groups x 16 lanes, 4 passes; idx from smem; unroll-4 row loads
    {
        int grp = tid >> 4, lane16 = tid & 15;
#pragma unroll
        for (int pass = 0; pass < 4; pass++) {
            int nl = pass * 16 + grp;
            int node = nb + nl;
            float4 acc = make_float4(0.f, 0.f, 0.f, 0.f);
            if (node < nNodes) {
                acc = *reinterpret_cast<const float4*>(
                    &hin[(size_t)node * HID + 4 * lane16]);   // self term
                int s = __ldg(&g_off[node]) - eBase;
                int d = __ldg(&g_deg[node]);
                if (s + d <= eStage) {
#pragma unroll 4
                    for (int i = 0; i < d; i++) {
                        int src = sEdge[s + i];
                        float4 v = __ldg(reinterpret_cast<const float4*>(
                            &hin[(size_t)src * HID + 4 * lane16]));
                        acc.x += v.x; acc.y += v.y; acc.z += v.z; acc.w += v.w;
                    }
                } else {
#pragma unroll 4
                    for (int i = 0; i < d; i++) {
                        int src = __ldg(&g_csr[eBase + s + i]);
                        float4 v = __ldg(reinterpret_cast<const float4*>(
                            &hin[(size_t)src * HID + 4 * lane16]));
                        acc.x += v.x; acc.y += v.y; acc.z += v.z; acc.w += v.w;
                    }
                }
            }
            float2 s0 = tf32_split(acc.x), s1 = tf32_split(acc.y),
                   s2 = tf32_split(acc.z), s3 = tf32_split(acc.w);
            *(float4*)&sInHi[nl * LDAA + 4 * lane16] = make_float4(s0.x, s1.x, s2.x, s3.x);
            *(float4*)&sInLo[nl * LDAA + 4 * lane16] = make_float4(s0.y, s1.y, s2.y, s3.y);
        }
    }
    __syncthreads();

    int wid = tid >> 5, lane = tid & 31;
    int gid = lane >> 2, tig = lane & 3;
    int m = (wid & 3) * 16;
    int nbase = (wid >> 2) * 32;

    float c[4][4];
    // ---- phase 1: mid = relu(in @ w1 + b1) ----
#pragma unroll
    for (int j = 0; j < 4; j++) {
        float2 bb = __ldg(reinterpret_cast<const float2*>(&b1[nbase + 8 * j + 2 * tig]));
        c[j][0] = bb.x; c[j][1] = bb.y; c[j][2] = bb.x; c[j][3] = bb.y;
    }
    tcgemm(c, sInHi, sInLo, sWHi, sWLo, m, nbase, gid, tig);
    __syncthreads();

    // epi1: relu + split back into A tiles; stage w2 into W tiles
#pragma unroll
    for (int j = 0; j < 4; j++) {
        int n0 = nbase + 8 * j + 2 * tig;
        int r0 = m + gid, r1 = r0 + 8;
        float2 s0 = tf32_split(fmaxf(c[j][0], 0.f));
        float2 s1 = tf32_split(fmaxf(c[j][1], 0.f));
        float2 s2 = tf32_split(fmaxf(c[j][2], 0.f));
        float2 s3 = tf32_split(fmaxf(c[j][3], 0.f));
        *(float2*)&sInHi[r0 * LDAA + n0] = make_float2(s0.x, s1.x);
        *(float2*)&sInLo[r0 * LDAA + n0] = make_float2(s0.y, s1.y);
        *(float2*)&sInHi[r1 * LDAA + n0] = make_float2(s2.x, s3.x);
        *(float2*)&sInLo[r1 * LDAA + n0] = make_float2(s2.y, s3.y);
    }
#pragma unroll
    for (int j = 0; j < 4; j++) {
        int idx = tid + j * 256;
        int k = idx >> 4;
        int n4 = (idx & 15) << 2;
        float4 w = __ldg(reinterpret_cast<const float4*>(w2) + idx);
        float2 s0 = tf32_split(w.x), s1 = tf32_split(w.y),
               s2 = tf32_split(w.z), s3 = tf32_split(w.w);
        *(float4*)&sWHi[k * LDAW + n4] = make_float4(s0.x, s1.x, s2.x, s3.x);
        *(float4*)&sWLo[k * LDAW + n4] = make_float4(s0.y, s1.y, s2.y, s3.y);
    }
    __syncthreads();

    // ---- phase 2: hout = relu(mid @ w2 + b2) + hin ----
#pragma unroll
    for (int j = 0; j < 4; j++) {
        float2 bb = __ldg(reinterpret_cast<const float2*>(&b2[nbase + 8 * j + 2 * tig]));
        c[j][0] = bb.x; c[j][1] = bb.y; c[j][2] = bb.x; c[j][3] = bb.y;
    }
    tcgemm(c, sInHi, sInLo, sWHi, sWLo, m, nbase, gid, tig);

    // epi2: relu + skip + store (+ pool on last layer)
#pragma unroll
    for (int j = 0; j < 4; j++) {
        int n0 = nbase + 8 * j + 2 * tig;
#pragma unroll
        for (int half = 0; half < 2; half++) {
            int r = m + gid + 8 * half;
            int node = nb + r;
            if (node < nNodes) {
                float cx = c[j][2 * half], cy = c[j][2 * half + 1];
                size_t gbi = (size_t)node * HID + n0;
                float2 skip = __ldg(reinterpret_cast<const float2*>(&hin[gbi]));
                float2 r2 = make_float2(fmaxf(cx, 0.f) + skip.x,
                                        fmaxf(cy, 0.f) + skip.y);
                *reinterpret_cast<float2*>(&hout[gbi]) = r2;
                if (isLast) {
                    int g = __ldg(&batch[node]);
                    if ((unsigned)g < NGRAPHS)
                        red_add_v2(&g_pooled[g * HID + n0], r2);
                }
            }
        }
    }
}

// ===========================================================================
// Final: out = pooled @ w_fc + b_fc   [128,64] @ [64,32]
// ===========================================================================
__global__ __launch_bounds__(256) void k_final(const float* __restrict__ w_fc,
                                               const float* __restrict__ b_fc,
                                               float* __restrict__ out) {
    int t = blockIdx.x * blockDim.x + threadIdx.x;
    if (t >= NGRAPHS * LAT) return;
    int g = t >> 5;
    int l = t & 31;
    float acc = b_fc[l];
#pragma unroll
    for (int k = 0; k < HID; k++)
        acc += g_pooled[g * HID + k] * w_fc[k * LAT + l];
    out[t] = acc;
}

// ===========================================================================
// Launch
// ===========================================================================
extern "C" void kernel_launch(void* const* d_in, const int* in_sizes, int n_in,
                              void* d_out, int out_size) {
    const float* x    = (const float*)d_in[0];
    const int*   ei   = (const int*)d_in[1];
    const int*   batch= (const int*)d_in[2];
    const float* w_in = (const float*)d_in[3];
    const float* b_in = (const float*)d_in[4];
    const float* w1   = (const float*)d_in[5];
    const float* b1   = (const float*)d_in[6];
    const float* w2   = (const float*)d_in[7];
    const float* b2   = (const float*)d_in[8];
    const float* w_fc = (const float*)d_in[9];
    const float* b_fc = (const float*)d_in[10];
    float* out = (float*)d_out;

    int nNodes = in_sizes[0] / IN_DIM;
    int nEdges = in_sizes[1] / 2;
    if (nNodes > NMAX) nNodes = NMAX;
    if (nEdges > EMAX) nEdges = EMAX;

    int nodeBlocks = (nNodes + 63) / 64;
    int edgeBlocks = (nEdges + 255) / 256;
    int nThreadBlocks = (nNodes + 255) / 256;
    int nChunks = (nNodes + 1023) / 1024;

    static int smemSet = 0;
    if (!smemSet) {
        cudaFuncSetAttribute(k_mlp_tc, cudaFuncAttributeMaxDynamicSharedMemorySize,
                             SMEM_BYTES);
        smemSet = 1;
    }

    float *hA, *hB;
    cudaGetSymbolAddress((void**)&hA, g_hA);
    cudaGetSymbolAddress((void**)&hB, g_hB);

    // CSR build (reused across all 3 layers)
    k_zero_init<<<nThreadBlocks, 256>>>(nNodes);
    k_hist<<<edgeBlocks, 256>>>(ei, nEdges, nNodes);
    k_scan1<<<nChunks, 1024>>>(nNodes);
    k_scan2<<<1, 128>>>(nChunks);
    k_scan3<<<nThreadBlocks, 256>>>(nNodes);
    k_fill<<<edgeBlocks, 256>>>(ei, nEdges, nNodes);

    k_proj<<<nodeBlocks, 256>>>(x, w_in, b_in, nNodes);

    const float* cur = hA;
    float* nxt = hB;
    for (int i = 0; i < 3; i++) {
        k_mlp_tc<<<nodeBlocks, 256, SMEM_BYTES>>>(
            cur, nxt,
            w1 + (size_t)i * HID * HID, b1 + (size_t)i * HID,
            w2 + (size_t)i * HID * HID, b2 + (size_t)i * HID,
            batch, (i == 2) ? 1 : 0, nNodes);
        const float* tmp = nxt;
        nxt = (float*)cur;
        cur = tmp;
    }

    k_final<<<(NGRAPHS * LAT + 255) / 256, 256>>>(w_fc, b_fc, out);
}